// round 3
// baseline (speedup 1.0000x reference)
#include <cuda_runtime.h>
#include <cstdint>

// FPSampler: farthest point sampling, B=16, N=131072, npoint=1024.
// 16 clusters x 8 CTAs, 512 threads/CTA, one CTA per SM (single wave).
// xyz planes resident in 192KB SMEM per CTA, distances in registers.
// Winner exchange: DSMEM weak stores + remote mbarrier.arrive.release.cluster
// (double-buffered, count=8), consumers try_wait.parity.acquire.cluster.

#define BB 16
#define NN 131072
#define NP 1024
#define GG 8                     // CTAs per cluster (batch group)
#define PTS (NN / GG)            // 16384 points per CTA
#define NT 512                   // threads per CTA
#define NW (NT / 32)             // 16 warps
#define JJ 8                     // float4 chunks per thread (8*4 = 32 points)
#define GRID (BB * GG)           // 128 CTAs
#define SMEM_BYTES (3 * PTS * sizeof(float))

struct StartArg { int s[BB]; };

// ---------------- helpers ---------------------------------------------------
__device__ __forceinline__ unsigned redux_max_u32(unsigned v) {
    unsigned r;
    asm("redux.sync.max.u32 %0, %1, 0xffffffff;" : "=r"(r) : "r"(v));
    return r;
}
__device__ __forceinline__ uint32_t smem_u32(const void* p) {
    uint32_t a;
    asm("{ .reg .u64 t; cvta.to.shared.u64 t, %1; cvt.u32.u64 %0, t; }"
        : "=r"(a) : "l"(p));
    return a;
}
__device__ __forceinline__ uint32_t mapa_u32(uint32_t laddr, uint32_t rank) {
    uint32_t r;
    asm("mapa.shared::cluster.u32 %0, %1, %2;" : "=r"(r) : "r"(laddr), "r"(rank));
    return r;
}
__device__ __forceinline__ void st_remote_u64(uint32_t raddr, unsigned long long v) {
    asm volatile("st.shared::cluster.b64 [%0], %1;" :: "r"(raddr), "l"(v) : "memory");
}
__device__ __forceinline__ void st_remote_u32(uint32_t raddr, uint32_t v) {
    asm volatile("st.shared::cluster.b32 [%0], %1;" :: "r"(raddr), "r"(v) : "memory");
}
__device__ __forceinline__ void mbar_init(uint32_t addr, uint32_t cnt) {
    asm volatile("mbarrier.init.shared.b64 [%0], %1;" :: "r"(addr), "r"(cnt) : "memory");
}
// remote arrive with release at cluster scope (publishes prior weak stores)
__device__ __forceinline__ void mbar_arrive_remote(uint32_t raddr) {
    asm volatile("mbarrier.arrive.release.cluster.shared::cluster.b64 _, [%0];"
                 :: "r"(raddr) : "memory");
}
__device__ __forceinline__ void mbar_wait_parity_acq_cluster(uint32_t addr,
                                                             uint32_t parity) {
    asm volatile(
        "{\n\t"
        ".reg .pred P1;\n\t"
        "WAIT_LOOP_%=:\n\t"
        "mbarrier.try_wait.parity.acquire.cluster.shared::cta.b64 P1, [%0], %1, 0x989680;\n\t"
        "@P1 bra.uni WAIT_DONE_%=;\n\t"
        "bra.uni WAIT_LOOP_%=;\n\t"
        "WAIT_DONE_%=:\n\t"
        "}"
        :: "r"(addr), "r"(parity) : "memory");
}
__device__ __forceinline__ unsigned long long pack2(float a, float b) {
    unsigned long long r;
    asm("mov.b64 %0, {%1, %2};" : "=l"(r) : "f"(a), "f"(b));
    return r;
}
__device__ __forceinline__ void unpack2(unsigned long long v, float& a, float& b) {
    asm("mov.b64 {%0, %1}, %2;" : "=f"(a), "=f"(b) : "l"(v));
}

__global__ void __launch_bounds__(NT, 1) __cluster_dims__(GG, 1, 1)
fps_main_kernel(const float* __restrict__ xyz, float* __restrict__ out, StartArg st)
{
    extern __shared__ float smem[];
    float* xs = smem;
    float* ys = smem + PTS;
    float* zs = smem + 2 * PTS;
    const float4* xs4 = (const float4*)xs;
    const float4* ys4 = (const float4*)ys;
    const float4* zs4 = (const float4*)zs;

    __shared__ unsigned long long wred[NW];
    __shared__ unsigned long long slot_pk[2][GG];
    __shared__ unsigned long long slot_xy[2][GG];
    __shared__ float              slot_z [2][GG];
    __shared__ alignas(8) unsigned long long mbar[2];

    const int cta  = blockIdx.x;
    const int b    = cta >> 3;       // batch (GG == 8)
    const int c    = cta & 7;        // rank within cluster
    const int t    = threadIdx.x;
    const int lane = t & 31;
    const int warp = t >> 5;
    const int base = c * PTS;        // first global point index of this CTA

    const float* xb = xyz + (size_t)b * NN * 3;
    float* out_xyz = out;
    float* out_idx = out + (size_t)BB * NP * 3;

    if (t == 0) {
        mbar_init(smem_u32(&mbar[0]), GG);
        mbar_init(smem_u32(&mbar[1]), GG);
    }

    // One-time load of this CTA's point slab into SMEM planes.
    for (int p = t; p < PTS; p += NT) {
        const float* src = xb + (size_t)(base + p) * 3;
        xs[p] = src[0];
        ys[p] = src[1];
        zs[p] = src[2];
    }
    __syncthreads();
    // one-time cluster barrier: peers' mbarriers initialized before any arrive
    asm volatile("barrier.cluster.arrive.aligned;" ::: "memory");
    asm volatile("barrier.cluster.wait.aligned;"   ::: "memory");

    float dist[JJ][4];
#pragma unroll
    for (int j = 0; j < JJ; j++)
#pragma unroll
        for (int e = 0; e < 4; e++) dist[j][e] = 1e10f;   // INF from reference

    // First centroid = start[b].
    const int fi = st.s[b];
    float cx = xb[(size_t)fi * 3 + 0];
    float cy = xb[(size_t)fi * 3 + 1];
    float cz = xb[(size_t)fi * 3 + 2];

    if (c == 0 && t == 0) {
        size_t o3 = (size_t)b * NP * 3;
        out_xyz[o3 + 0] = cx;
        out_xyz[o3 + 1] = cy;
        out_xyz[o3 + 2] = cz;
        out_idx[(size_t)b * NP] = (float)fi;
    }

    const uint32_t spk = smem_u32(&slot_pk[0][0]);
    const uint32_t sxy = smem_u32(&slot_xy[0][0]);
    const uint32_t sz  = smem_u32(&slot_z [0][0]);
    const uint32_t smb = smem_u32(&mbar[0]);

    for (int it = 1; it < NP; it++) {
        const int buf = it & 1;
        const uint32_t ph = (uint32_t)(((it - 1) >> 1) & 1);

        // ---- distance update + local argmax (first-index semantics) ----
        // exact reference math: scalar rn ops, (dx*dx + dy*dy) + dz*dz
        float bestv = -1.0f;
        int bestp = 0;
#pragma unroll
        for (int j = 0; j < JJ; j++) {
            const int c0 = j * NT + t;            // chunk; points 4c0..4c0+3 ascending
            float4 x4 = xs4[c0];
            float4 y4 = ys4[c0];
            float4 z4 = zs4[c0];

            float dx, dy, dz, d, nd;

            dx = __fadd_rn(x4.x, -cx);
            dy = __fadd_rn(y4.x, -cy);
            dz = __fadd_rn(z4.x, -cz);
            d  = __fadd_rn(__fadd_rn(__fmul_rn(dx, dx), __fmul_rn(dy, dy)),
                           __fmul_rn(dz, dz));
            nd = fminf(dist[j][0], d); dist[j][0] = nd;
            if (nd > bestv) { bestv = nd; bestp = 4 * c0 + 0; }

            dx = __fadd_rn(x4.y, -cx);
            dy = __fadd_rn(y4.y, -cy);
            dz = __fadd_rn(z4.y, -cz);
            d  = __fadd_rn(__fadd_rn(__fmul_rn(dx, dx), __fmul_rn(dy, dy)),
                           __fmul_rn(dz, dz));
            nd = fminf(dist[j][1], d); dist[j][1] = nd;
            if (nd > bestv) { bestv = nd; bestp = 4 * c0 + 1; }

            dx = __fadd_rn(x4.z, -cx);
            dy = __fadd_rn(y4.z, -cy);
            dz = __fadd_rn(z4.z, -cz);
            d  = __fadd_rn(__fadd_rn(__fmul_rn(dx, dx), __fmul_rn(dy, dy)),
                           __fmul_rn(dz, dz));
            nd = fminf(dist[j][2], d); dist[j][2] = nd;
            if (nd > bestv) { bestv = nd; bestp = 4 * c0 + 2; }

            dx = __fadd_rn(x4.w, -cx);
            dy = __fadd_rn(y4.w, -cy);
            dz = __fadd_rn(z4.w, -cz);
            d  = __fadd_rn(__fadd_rn(__fmul_rn(dx, dx), __fmul_rn(dy, dy)),
                           __fmul_rn(dz, dz));
            nd = fminf(dist[j][3], d); dist[j][3] = nd;
            if (nd > bestv) { bestv = nd; bestp = 4 * c0 + 3; }
        }

        // ---- warp reduce via 2x REDUX (value bits, then ~idx among matches) ----
        const unsigned mybits = __float_as_uint(bestv);      // d>=0 -> monotone bits
        const unsigned maxb = redux_max_u32(mybits);
        const unsigned cand = (mybits == maxb)
                            ? (0xFFFFFFFFu - (unsigned)(base + bestp)) : 0u;
        const unsigned maxc = redux_max_u32(cand);           // tie -> smallest idx
        if (lane == 0)
            wred[warp] = ((unsigned long long)maxb << 32) | maxc;
        __syncthreads();

        // ---- CTA reduce + DSMEM publish (warp 0) ----
        if (warp == 0) {
            unsigned long long best = 0ull;
#pragma unroll
            for (int w = 0; w < NW; w++) {
                unsigned long long v = wred[w];
                if (v > best) best = v;
            }
            if (lane < GG) {                  // lanes 0..7: one peer rank each
                unsigned gw = 0xFFFFFFFFu - (unsigned)(best & 0xFFFFFFFFull);
                int lp = (int)gw - base;      // CTA-local winner (broadcast LDS)
                unsigned long long xy = pack2(xs[lp], ys[lp]);
                uint32_t wzb = __float_as_uint(zs[lp]);
                uint32_t o8 = (uint32_t)((buf * GG + c) * 8);
                uint32_t o4 = (uint32_t)((buf * GG + c) * 4);
                st_remote_u64(mapa_u32(spk + o8, (uint32_t)lane), best);
                st_remote_u64(mapa_u32(sxy + o8, (uint32_t)lane), xy);
                st_remote_u32(mapa_u32(sz  + o4, (uint32_t)lane), wzb);
                mbar_arrive_remote(mapa_u32(smb + (uint32_t)(buf * 8), (uint32_t)lane));
            }
        }

        // ---- all threads wait for 8 arrivals, then pick group winner locally ----
        mbar_wait_parity_acq_cluster(smb + (uint32_t)(buf * 8), ph);

        unsigned long long wb = 0ull; int wc = 0;
#pragma unroll
        for (int jj = 0; jj < GG; jj++) {
            unsigned long long v = slot_pk[buf][jj];
            if (v > wb) { wb = v; wc = jj; }
        }
        unpack2(slot_xy[buf][wc], cx, cy);
        cz = slot_z[buf][wc];

        if (c == 0 && t == 0) {
            unsigned widx = 0xFFFFFFFFu - (unsigned)(wb & 0xFFFFFFFFull);
            size_t o3 = ((size_t)b * NP + it) * 3;
            out_xyz[o3 + 0] = cx;
            out_xyz[o3 + 1] = cy;
            out_xyz[o3 + 2] = cz;
            out_idx[(size_t)b * NP + it] = (float)widx;
        }
    }

    // final cluster barrier: no CTA exits while peers may still touch its SMEM
    asm volatile("barrier.cluster.arrive.aligned;" ::: "memory");
    asm volatile("barrier.cluster.wait.aligned;"   ::: "memory");
}

// ---------------------------------------------------------------------------
// Host-side reproduction of JAX Threefry RNG for `start` (verified exact R1):
//   start = randint(fold_in(key(0), 1), (16,), 0, 131072), partitionable mode.
// ---------------------------------------------------------------------------
static void tf2x32(uint32_t k0, uint32_t k1, uint32_t c0, uint32_t c1,
                   uint32_t* o0, uint32_t* o1)
{
    uint32_t ks[3] = { k0, k1, k0 ^ k1 ^ 0x1BD11BDAu };
    uint32_t x0 = c0 + ks[0];
    uint32_t x1 = c1 + ks[1];
    static const int rot[2][4] = { {13, 15, 26, 6}, {17, 29, 16, 24} };
    for (int i = 0; i < 5; i++) {
        const int* r = rot[i & 1];
        for (int j = 0; j < 4; j++) {
            x0 += x1;
            x1 = (x1 << r[j]) | (x1 >> (32 - r[j]));
            x1 ^= x0;
        }
        x0 += ks[(i + 1) % 3];
        x1 += ks[(i + 2) % 3] + (uint32_t)(i + 1);
    }
    *o0 = x0;
    *o1 = x1;
}

static void compute_start(int* s)
{
    uint32_t K0, K1;
    tf2x32(0u, 0u, 0u, 1u, &K0, &K1);       // fold_in(key(0), 1)
    uint32_t b0, b1;
    tf2x32(K0, K1, 0u, 1u, &b0, &b1);       // partitionable split, lower key
    for (int i = 0; i < BB; i++) {
        uint32_t y0, y1;
        tf2x32(b0, b1, 0u, (uint32_t)i, &y0, &y1);
        s[i] = (int)((y0 ^ y1) & (uint32_t)(NN - 1));   // span = 2^17
    }
}

extern "C" void kernel_launch(void* const* d_in, const int* in_sizes, int n_in,
                              void* d_out, int out_size)
{
    const float* xyz = (const float*)d_in[0];
    float* out = (float*)d_out;

    StartArg st;
    compute_start(st.s);

    cudaFuncSetAttribute(fps_main_kernel,
                         cudaFuncAttributeMaxDynamicSharedMemorySize,
                         (int)SMEM_BYTES);

    fps_main_kernel<<<GRID, NT, SMEM_BYTES>>>(xyz, out, st);
}

// round 4
// speedup vs baseline: 1.2917x; 1.2917x over previous
#include <cuda_runtime.h>
#include <cstdint>

// FPSampler: farthest point sampling, B=16, N=131072, npoint=1024.
// 16 groups x 8 CTAs (plain launch, no clusters), 512 threads/CTA, 1 CTA/SM.
// xyz planes resident in 192KB SMEM, distances in registers.
// Compute: packed f32x2 rn arithmetic fed directly from LDS.128 (bit-exact).
// Exchange: L2 slots + monotonic counter, atom.add.release / ld.acquire,
// parallel 8-slot loads by lanes 0-7, redux max, shfl winner coords.

#define BB 16
#define NN 131072
#define NP 1024
#define GG 8                     // CTAs per batch group
#define PTS (NN / GG)            // 16384 points per CTA
#define NT 512                   // threads per CTA
#define NW (NT / 32)             // 16 warps
#define JJ 8                     // float4 chunks per thread (8*4 = 32 points)
#define GRID (BB * GG)           // 128 CTAs
#define SMEM_BYTES (3 * PTS * sizeof(float))

struct alignas(16) Slot {
    unsigned long long pk;       // (dist_bits << 32) | (0xFFFFFFFF - idx)
    unsigned long long xy;       // packed (x, y)
    unsigned long long zb;       // z bits in low 32
    unsigned long long pad;
};

__device__ Slot g_slots[2][BB][GG];
__device__ unsigned g_cnt[BB * 32];     // one counter per group, own 128B line

struct StartArg { int s[BB]; };

__global__ void fps_init_kernel() {
    int i = threadIdx.x;
    if (i < BB) g_cnt[i * 32] = 0u;
}

// ---------------- helpers ---------------------------------------------------
__device__ __forceinline__ unsigned redux_max_u32(unsigned v) {
    unsigned r;
    asm("redux.sync.max.u32 %0, %1, 0xffffffff;" : "=r"(r) : "r"(v));
    return r;
}
__device__ __forceinline__ unsigned long long f2add(unsigned long long a,
                                                    unsigned long long b) {
    unsigned long long r;
    asm("add.rn.f32x2 %0, %1, %2;" : "=l"(r) : "l"(a), "l"(b));
    return r;
}
__device__ __forceinline__ unsigned long long f2mul(unsigned long long a,
                                                    unsigned long long b) {
    unsigned long long r;
    asm("mul.rn.f32x2 %0, %1, %2;" : "=l"(r) : "l"(a), "l"(b));
    return r;
}
__device__ __forceinline__ unsigned long long pack2(float a, float b) {
    unsigned long long r;
    asm("mov.b64 %0, {%1, %2};" : "=l"(r) : "f"(a), "f"(b));
    return r;
}
__device__ __forceinline__ void unpack2(unsigned long long v, float& a, float& b) {
    asm("mov.b64 {%0, %1}, %2;" : "=f"(a), "=f"(b) : "l"(v));
}
__device__ __forceinline__ void atom_add_release(unsigned* p, unsigned v) {
    unsigned o;
    asm volatile("atom.release.gpu.global.add.u32 %0, [%1], %2;"
                 : "=r"(o) : "l"(p), "r"(v) : "memory");
}
__device__ __forceinline__ unsigned ld_acquire(const unsigned* p) {
    unsigned v;
    asm volatile("ld.acquire.gpu.global.u32 %0, [%1];" : "=r"(v) : "l"(p) : "memory");
    return v;
}
__device__ __forceinline__ void st_cg_v2(void* p, unsigned long long a,
                                         unsigned long long b) {
    asm volatile("st.global.cg.v2.u64 [%0], {%1, %2};"
                 :: "l"(p), "l"(a), "l"(b) : "memory");
}
__device__ __forceinline__ void ld_cg_v2(const void* p, unsigned long long& a,
                                         unsigned long long& b) {
    asm volatile("ld.global.cg.v2.u64 {%0, %1}, [%2];"
                 : "=l"(a), "=l"(b) : "l"(p));
}
__device__ __forceinline__ unsigned long long ld_cg_u64(const void* p) {
    unsigned long long v;
    asm volatile("ld.global.cg.u64 %0, [%1];" : "=l"(v) : "l"(p));
    return v;
}

__global__ void __launch_bounds__(NT, 1)
fps_main_kernel(const float* __restrict__ xyz, float* __restrict__ out, StartArg st)
{
    extern __shared__ float smem[];
    float* xs = smem;
    float* ys = smem + PTS;
    float* zs = smem + 2 * PTS;
    const ulonglong2* xs2 = (const ulonglong2*)xs;   // 1 elt = 4 floats = 2 pairs
    const ulonglong2* ys2 = (const ulonglong2*)ys;
    const ulonglong2* zs2 = (const ulonglong2*)zs;

    __shared__ unsigned long long wred[NW];
    __shared__ unsigned long long bc_xy;
    __shared__ unsigned long long bc_pk;
    __shared__ unsigned bc_zb;

    const int cta  = blockIdx.x;
    const int b    = cta >> 3;       // batch (GG == 8)
    const int c    = cta & 7;        // CTA within group
    const int t    = threadIdx.x;
    const int lane = t & 31;
    const int warp = t >> 5;
    const int base = c * PTS;

    const float* xb = xyz + (size_t)b * NN * 3;
    float* out_xyz = out;
    float* out_idx = out + (size_t)BB * NP * 3;

    // One-time load of this CTA's point slab into SMEM planes.
    for (int p = t; p < PTS; p += NT) {
        const float* src = xb + (size_t)(base + p) * 3;
        xs[p] = src[0];
        ys[p] = src[1];
        zs[p] = src[2];
    }

    float dist[JJ][4];
#pragma unroll
    for (int j = 0; j < JJ; j++)
#pragma unroll
        for (int e = 0; e < 4; e++) dist[j][e] = 1e10f;   // INF from reference

    // First centroid = start[b].
    const int fi = st.s[b];
    float cx = xb[(size_t)fi * 3 + 0];
    float cy = xb[(size_t)fi * 3 + 1];
    float cz = xb[(size_t)fi * 3 + 2];

    if (c == 0 && t == 0) {
        size_t o3 = (size_t)b * NP * 3;
        out_xyz[o3 + 0] = cx;
        out_xyz[o3 + 1] = cy;
        out_xyz[o3 + 2] = cz;
        out_idx[(size_t)b * NP] = (float)fi;
    }
    __syncthreads();

    unsigned* cnt = &g_cnt[b * 32];

    for (int it = 1; it < NP; it++) {
        const int buf = it & 1;
        // packed negated centroid (x - c == x + (-c), bit-exact)
        const unsigned long long ncx2 = pack2(-cx, -cx);
        const unsigned long long ncy2 = pack2(-cy, -cy);
        const unsigned long long ncz2 = pack2(-cz, -cz);

        // ---- distance update (packed f32x2, exact rn) + value-only max ----
        float bv0 = -1.0f, bv1 = -1.0f, bv2 = -1.0f, bv3 = -1.0f;
#pragma unroll
        for (int j = 0; j < JJ; j++) {
            const int c0 = j * NT + t;            // chunk; points 4c0..4c0+3
            ulonglong2 xq = xs2[c0];              // (x0,x1),(x2,x3) pairs, free
            ulonglong2 yq = ys2[c0];
            ulonglong2 zq = zs2[c0];

            unsigned long long dxa = f2add(xq.x, ncx2);
            unsigned long long dxb = f2add(xq.y, ncx2);
            unsigned long long dya = f2add(yq.x, ncy2);
            unsigned long long dyb = f2add(yq.y, ncy2);
            unsigned long long dza = f2add(zq.x, ncz2);
            unsigned long long dzb = f2add(zq.y, ncz2);
            // exact reference order: (dx*dx + dy*dy) + dz*dz
            unsigned long long sa =
                f2add(f2add(f2mul(dxa, dxa), f2mul(dya, dya)), f2mul(dza, dza));
            unsigned long long sb =
                f2add(f2add(f2mul(dxb, dxb), f2mul(dyb, dyb)), f2mul(dzb, dzb));

            float d0, d1, d2, d3;
            unpack2(sa, d0, d1);
            unpack2(sb, d2, d3);

            float nd;
            nd = fminf(dist[j][0], d0); dist[j][0] = nd; bv0 = fmaxf(bv0, nd);
            nd = fminf(dist[j][1], d1); dist[j][1] = nd; bv1 = fmaxf(bv1, nd);
            nd = fminf(dist[j][2], d2); dist[j][2] = nd; bv2 = fmaxf(bv2, nd);
            nd = fminf(dist[j][3], d3); dist[j][3] = nd; bv3 = fmaxf(bv3, nd);
        }
        const float bestv = fmaxf(fmaxf(bv0, bv1), fmaxf(bv2, bv3));

        // ---- warp reduce: max bits, then post-hoc first-index scan ----
        const unsigned mybits = __float_as_uint(bestv);   // d>=0 -> monotone bits
        const unsigned maxb = redux_max_u32(mybits);
        const float maxvf = __uint_as_float(maxb);
        unsigned cand = 0;                                // ~idx of my first match
#pragma unroll
        for (int j = 0; j < JJ; j++)
#pragma unroll
            for (int e = 0; e < 4; e++)
                if (dist[j][e] == maxvf && cand == 0)
                    cand = 0xFFFFFFFFu - (unsigned)(base + 4 * (j * NT + t) + e);
        const unsigned maxc = redux_max_u32(cand);        // tie -> smallest idx
        if (lane == 0)
            wred[warp] = ((unsigned long long)maxb << 32) | maxc;
        __syncthreads();

        // ---- warp 0: CTA reduce + publish + exchange ----
        if (warp == 0) {
            unsigned long long wv = (lane < NW) ? wred[lane] : 0ull;
            unsigned hb = (unsigned)(wv >> 32);
            unsigned maxhb = redux_max_u32(hb);
            unsigned lb = (hb == maxhb) ? (unsigned)(wv & 0xFFFFFFFFull) : 0u;
            unsigned maxlb = redux_max_u32(lb);
            const unsigned long long best =
                ((unsigned long long)maxhb << 32) | maxlb;

            if (lane == 0) {
                unsigned gw = 0xFFFFFFFFu - maxlb;
                int lp = (int)gw - base;                  // CTA-local winner
                Slot* sl = &g_slots[buf][b][c];
                st_cg_v2(&sl->pk, best, pack2(xs[lp], ys[lp]));
                asm volatile("st.global.cg.u64 [%0], %1;"
                             :: "l"(&sl->zb),
                                "l"((unsigned long long)__float_as_uint(zs[lp]))
                             : "memory");
                atom_add_release(cnt, 1u);                // release prior stores

                const unsigned target = (unsigned)(GG * it);
                while (ld_acquire(cnt) < target) { }
            }
            __syncwarp();

            // lanes 0..7: load all 8 slots in parallel
            unsigned long long pk_j = 0ull, xy_j = 0ull, zb_j = 0ull;
            if (lane < GG) {
                const Slot* sl = &g_slots[buf][b][lane];
                ld_cg_v2(&sl->pk, pk_j, xy_j);
                zb_j = ld_cg_u64(&sl->zb);
            }
            unsigned hj = (unsigned)(pk_j >> 32);
            unsigned maxh = redux_max_u32(hj);
            unsigned lj = (hj == maxh) ? (unsigned)(pk_j & 0xFFFFFFFFull) : 0u;
            unsigned maxl = redux_max_u32(lj);
            const unsigned long long wb =
                ((unsigned long long)maxh << 32) | maxl;

            unsigned m = __ballot_sync(0xFFFFFFFFu, lane < GG && pk_j == wb);
            int wl = __ffs(m) - 1;
            unsigned long long wxy = __shfl_sync(0xFFFFFFFFu, xy_j, wl);
            unsigned long long wzb = __shfl_sync(0xFFFFFFFFu, zb_j, wl);

            if (lane == 0) {
                bc_pk = wb;
                bc_xy = wxy;
                bc_zb = (unsigned)wzb;
            }
        }
        __syncthreads();

        unpack2(bc_xy, cx, cy);
        cz = __uint_as_float(bc_zb);

        if (c == 0 && t == 0) {
            unsigned widx = 0xFFFFFFFFu - (unsigned)(bc_pk & 0xFFFFFFFFull);
            size_t o3 = ((size_t)b * NP + it) * 3;
            out_xyz[o3 + 0] = cx;
            out_xyz[o3 + 1] = cy;
            out_xyz[o3 + 2] = cz;
            out_idx[(size_t)b * NP + it] = (float)widx;
        }
    }
}

// ---------------------------------------------------------------------------
// Host-side reproduction of JAX Threefry RNG for `start` (verified exact R1):
//   start = randint(fold_in(key(0), 1), (16,), 0, 131072), partitionable mode.
// ---------------------------------------------------------------------------
static void tf2x32(uint32_t k0, uint32_t k1, uint32_t c0, uint32_t c1,
                   uint32_t* o0, uint32_t* o1)
{
    uint32_t ks[3] = { k0, k1, k0 ^ k1 ^ 0x1BD11BDAu };
    uint32_t x0 = c0 + ks[0];
    uint32_t x1 = c1 + ks[1];
    static const int rot[2][4] = { {13, 15, 26, 6}, {17, 29, 16, 24} };
    for (int i = 0; i < 5; i++) {
        const int* r = rot[i & 1];
        for (int j = 0; j < 4; j++) {
            x0 += x1;
            x1 = (x1 << r[j]) | (x1 >> (32 - r[j]));
            x1 ^= x0;
        }
        x0 += ks[(i + 1) % 3];
        x1 += ks[(i + 2) % 3] + (uint32_t)(i + 1);
    }
    *o0 = x0;
    *o1 = x1;
}

static void compute_start(int* s)
{
    uint32_t K0, K1;
    tf2x32(0u, 0u, 0u, 1u, &K0, &K1);       // fold_in(key(0), 1)
    uint32_t b0, b1;
    tf2x32(K0, K1, 0u, 1u, &b0, &b1);       // partitionable split, lower key
    for (int i = 0; i < BB; i++) {
        uint32_t y0, y1;
        tf2x32(b0, b1, 0u, (uint32_t)i, &y0, &y1);
        s[i] = (int)((y0 ^ y1) & (uint32_t)(NN - 1));   // span = 2^17
    }
}

extern "C" void kernel_launch(void* const* d_in, const int* in_sizes, int n_in,
                              void* d_out, int out_size)
{
    const float* xyz = (const float*)d_in[0];
    float* out = (float*)d_out;

    StartArg st;
    compute_start(st.s);

    cudaFuncSetAttribute(fps_main_kernel,
                         cudaFuncAttributeMaxDynamicSharedMemorySize,
                         (int)SMEM_BYTES);

    fps_init_kernel<<<1, 32>>>();
    fps_main_kernel<<<GRID, NT, SMEM_BYTES>>>(xyz, out, st);
}

// round 7
// speedup vs baseline: 1.4405x; 1.1152x over previous
#include <cuda_runtime.h>
#include <cstdint>

// FPSampler: farthest point sampling, B=16, N=131072, npoint=1024.
// 16 groups x 8 CTAs, 512 threads/CTA, 1 CTA/SM single wave.
// xyz planes resident in 192KB SMEM, distances in registers.
// Compute: packed f32x2 rn arithmetic fed from LDS.128 (bit-exact, proven R4).
// Exchange: R4 structure (warp-0-only, bc broadcast, trailing barrier) with the
// atomic counter replaced by self-validating tagged u64 slot words, polled by
// a WARP-UNIFORM loop (all lanes iterate together, exit via __all_sync).

#define BB 16
#define NN 131072
#define NP 1024
#define GG 8                     // CTAs per batch group
#define PTS (NN / GG)            // 16384 points per CTA
#define NT 512                   // threads per CTA
#define NW (NT / 32)             // 16 warps
#define JJ 8                     // float4 chunks per thread (8*4 = 32 points)
#define GRID (BB * GG)           // 128 CTAs
#define SMEM_BYTES (3 * PTS * sizeof(float))

// Slot: 4 aligned u64 words, EACH self-tagged with seq (=it); one 32B sector.
//   w0 = [seq:15 bits 49..63 | val:32 bits 17..48 | idx:17 bits 0..16]
//   wx/wy/wz = (seq << 32) | f32_bits
struct alignas(32) Slot4 {
    unsigned long long w0, wx, wy, wz;
};

__device__ Slot4 g_slot[2][BB][GG];

struct StartArg { int s[BB]; };

__global__ void fps_clear_kernel() {
    unsigned long long* p = (unsigned long long*)g_slot;
    int n = 2 * BB * GG * 4;
    for (int i = threadIdx.x; i < n; i += blockDim.x) p[i] = 0ull;
}

// ---------------- helpers ---------------------------------------------------
__device__ __forceinline__ unsigned redux_max_u32(unsigned v) {
    unsigned r;
    asm("redux.sync.max.u32 %0, %1, 0xffffffff;" : "=r"(r) : "r"(v));
    return r;
}
__device__ __forceinline__ unsigned long long f2add(unsigned long long a,
                                                    unsigned long long b) {
    unsigned long long r;
    asm("add.rn.f32x2 %0, %1, %2;" : "=l"(r) : "l"(a), "l"(b));
    return r;
}
__device__ __forceinline__ unsigned long long f2mul(unsigned long long a,
                                                    unsigned long long b) {
    unsigned long long r;
    asm("mul.rn.f32x2 %0, %1, %2;" : "=l"(r) : "l"(a), "l"(b));
    return r;
}
__device__ __forceinline__ unsigned long long pack2(float a, float b) {
    unsigned long long r;
    asm("mov.b64 %0, {%1, %2};" : "=l"(r) : "f"(a), "f"(b));
    return r;
}
__device__ __forceinline__ void unpack2(unsigned long long v, float& a, float& b) {
    asm("mov.b64 {%0, %1}, %2;" : "=f"(a), "=f"(b) : "l"(v));
}
__device__ __forceinline__ void st_cg_u64(void* p, unsigned long long v) {
    asm volatile("st.global.cg.u64 [%0], %1;" :: "l"(p), "l"(v) : "memory");
}
__device__ __forceinline__ unsigned long long ld_cg_u64(const void* p) {
    unsigned long long v;
    asm volatile("ld.global.cg.u64 %0, [%1];" : "=l"(v) : "l"(p) : "memory");
    return v;
}

__global__ void __launch_bounds__(NT, 1)
fps_main_kernel(const float* __restrict__ xyz, float* __restrict__ out, StartArg st)
{
    extern __shared__ float smem[];
    float* xs = smem;
    float* ys = smem + PTS;
    float* zs = smem + 2 * PTS;
    const ulonglong2* xs2 = (const ulonglong2*)xs;   // 1 elt = 4 floats = 2 pairs
    const ulonglong2* ys2 = (const ulonglong2*)ys;
    const ulonglong2* zs2 = (const ulonglong2*)zs;

    __shared__ unsigned long long wred[NW];
    __shared__ unsigned bc_x, bc_y, bc_z, bc_idx;

    const int cta  = blockIdx.x;
    const int b    = cta >> 3;       // batch (GG == 8)
    const int c    = cta & 7;        // CTA within group
    const int t    = threadIdx.x;
    const int lane = t & 31;
    const int warp = t >> 5;
    const int base = c * PTS;

    const float* xb = xyz + (size_t)b * NN * 3;
    float* out_xyz = out;
    float* out_idx = out + (size_t)BB * NP * 3;

    // One-time load of this CTA's point slab into SMEM planes.
    for (int p = t; p < PTS; p += NT) {
        const float* src = xb + (size_t)(base + p) * 3;
        xs[p] = src[0];
        ys[p] = src[1];
        zs[p] = src[2];
    }

    float dist[JJ][4];
#pragma unroll
    for (int j = 0; j < JJ; j++)
#pragma unroll
        for (int e = 0; e < 4; e++) dist[j][e] = 1e10f;   // INF from reference

    // First centroid = start[b].
    const int fi = st.s[b];
    float cx = xb[(size_t)fi * 3 + 0];
    float cy = xb[(size_t)fi * 3 + 1];
    float cz = xb[(size_t)fi * 3 + 2];

    if (c == 0 && t == 0) {
        size_t o3 = (size_t)b * NP * 3;
        out_xyz[o3 + 0] = cx;
        out_xyz[o3 + 1] = cy;
        out_xyz[o3 + 2] = cz;
        out_idx[(size_t)b * NP] = (float)fi;
    }
    __syncthreads();

    for (int it = 1; it < NP; it++) {
        const int buf = it & 1;
        // packed negated centroid (x - c == x + (-c), bit-exact)
        const unsigned long long ncx2 = pack2(-cx, -cx);
        const unsigned long long ncy2 = pack2(-cy, -cy);
        const unsigned long long ncz2 = pack2(-cz, -cz);

        // ---- distance update (packed f32x2, exact rn) + value-only max ----
        float bv0 = -1.0f, bv1 = -1.0f, bv2 = -1.0f, bv3 = -1.0f;
#pragma unroll
        for (int j = 0; j < JJ; j++) {
            const int c0 = j * NT + t;            // chunk; points 4c0..4c0+3
            ulonglong2 xq = xs2[c0];              // (x0,x1),(x2,x3) pairs, free
            ulonglong2 yq = ys2[c0];
            ulonglong2 zq = zs2[c0];

            unsigned long long dxa = f2add(xq.x, ncx2);
            unsigned long long dxb = f2add(xq.y, ncx2);
            unsigned long long dya = f2add(yq.x, ncy2);
            unsigned long long dyb = f2add(yq.y, ncy2);
            unsigned long long dza = f2add(zq.x, ncz2);
            unsigned long long dzb = f2add(zq.y, ncz2);
            // exact reference order: (dx*dx + dy*dy) + dz*dz
            unsigned long long sa =
                f2add(f2add(f2mul(dxa, dxa), f2mul(dya, dya)), f2mul(dza, dza));
            unsigned long long sb =
                f2add(f2add(f2mul(dxb, dxb), f2mul(dyb, dyb)), f2mul(dzb, dzb));

            float d0, d1, d2, d3;
            unpack2(sa, d0, d1);
            unpack2(sb, d2, d3);

            float nd;
            nd = fminf(dist[j][0], d0); dist[j][0] = nd; bv0 = fmaxf(bv0, nd);
            nd = fminf(dist[j][1], d1); dist[j][1] = nd; bv1 = fmaxf(bv1, nd);
            nd = fminf(dist[j][2], d2); dist[j][2] = nd; bv2 = fmaxf(bv2, nd);
            nd = fminf(dist[j][3], d3); dist[j][3] = nd; bv3 = fmaxf(bv3, nd);
        }
        const float bestv = fmaxf(fmaxf(bv0, bv1), fmaxf(bv2, bv3));

        // ---- warp reduce: max bits, then post-hoc first-index scan ----
        const unsigned mybits = __float_as_uint(bestv);   // d>=0 -> monotone bits
        const unsigned maxb = redux_max_u32(mybits);
        const float maxvf = __uint_as_float(maxb);
        unsigned cand = 0;                                // ~idx of my first match
#pragma unroll
        for (int j = 0; j < JJ; j++)
#pragma unroll
            for (int e = 0; e < 4; e++)
                if (dist[j][e] == maxvf && cand == 0)
                    cand = 0xFFFFFFFFu - (unsigned)(base + 4 * (j * NT + t) + e);
        const unsigned maxc = redux_max_u32(cand);        // tie -> smallest idx
        if (lane == 0)
            wred[warp] = ((unsigned long long)maxb << 32) | maxc;
        __syncthreads();

        // ---- warp 0 ONLY: CTA reduce + publish + tagged-slot exchange ----
        if (warp == 0) {
            unsigned long long wv = (lane < NW) ? wred[lane] : 0ull;
            unsigned hb = (unsigned)(wv >> 32);
            unsigned maxhb = redux_max_u32(hb);
            unsigned lb = (hb == maxhb) ? (unsigned)(wv & 0xFFFFFFFFull) : 0u;
            unsigned maxlb = redux_max_u32(lb);

            if (lane == 0) {
                unsigned gidx = 0xFFFFFFFFu - maxlb;      // global winner idx
                int lp = (int)gidx - base;                // CTA-local winner
                const unsigned long long seq32 = ((unsigned long long)it << 32);
                Slot4* sl = &g_slot[buf][b][c];
                st_cg_u64(&sl->wx, seq32 | __float_as_uint(xs[lp]));
                st_cg_u64(&sl->wy, seq32 | __float_as_uint(ys[lp]));
                st_cg_u64(&sl->wz, seq32 | __float_as_uint(zs[lp]));
                st_cg_u64(&sl->w0, ((unsigned long long)it << 49) |
                                   ((unsigned long long)maxhb << 17) |
                                   (unsigned long long)(gidx & 0x1FFFFu));
            }
            __syncwarp();

            // warp-UNIFORM tagged poll: every trip all lanes iterate together;
            // exit only via converged __all_sync. Lanes >= GG are vacuously ok.
            const Slot4* sl = &g_slot[buf][b][lane & 7];
            unsigned long long w0 = 0, wx = 0, wy = 0, wz = 0;
            const unsigned u = (unsigned)it;
            bool ok;
            do {
                if (lane < GG) {
                    w0 = ld_cg_u64(&sl->w0);
                    wx = ld_cg_u64(&sl->wx);
                    wy = ld_cg_u64(&sl->wy);
                    wz = ld_cg_u64(&sl->wz);
                    ok = ((unsigned)(w0 >> 49) == u) &
                         ((unsigned)(wx >> 32) == u) &
                         ((unsigned)(wy >> 32) == u) &
                         ((unsigned)(wz >> 32) == u);
                } else {
                    ok = true;
                }
            } while (!__all_sync(0xFFFFFFFFu, ok));

            unsigned val_j = 0u, nidx_j = 0u, xb_j = 0u, yb_j = 0u, zb_j = 0u;
            if (lane < GG) {
                val_j  = (unsigned)((w0 >> 17) & 0xFFFFFFFFull);
                nidx_j = 0xFFFFFFFFu - (unsigned)(w0 & 0x1FFFFull);
                xb_j = (unsigned)wx;
                yb_j = (unsigned)wy;
                zb_j = (unsigned)wz;
            }
            const unsigned maxh = redux_max_u32(val_j);
            const unsigned lj = (val_j == maxh) ? nidx_j : 0u;
            const unsigned maxl = redux_max_u32(lj);      // tie -> smallest idx
            const unsigned m = __ballot_sync(0xFFFFFFFFu,
                                lane < GG && val_j == maxh && nidx_j == maxl);
            const int wl = __ffs((int)m) - 1;
            const unsigned wxb = __shfl_sync(0xFFFFFFFFu, xb_j, wl);
            const unsigned wyb = __shfl_sync(0xFFFFFFFFu, yb_j, wl);
            const unsigned wzb = __shfl_sync(0xFFFFFFFFu, zb_j, wl);

            if (lane == 0) {
                bc_x = wxb;
                bc_y = wyb;
                bc_z = wzb;
                bc_idx = 0xFFFFFFFFu - maxl;              // global winner idx
            }
        }
        __syncthreads();

        cx = __uint_as_float(bc_x);
        cy = __uint_as_float(bc_y);
        cz = __uint_as_float(bc_z);

        if (c == 0 && t == 0) {
            size_t o3 = ((size_t)b * NP + it) * 3;
            out_xyz[o3 + 0] = cx;
            out_xyz[o3 + 1] = cy;
            out_xyz[o3 + 2] = cz;
            out_idx[(size_t)b * NP + it] = (float)bc_idx;
        }
    }
}

// ---------------------------------------------------------------------------
// Host-side reproduction of JAX Threefry RNG for `start` (verified exact R1):
//   start = randint(fold_in(key(0), 1), (16,), 0, 131072), partitionable mode.
// ---------------------------------------------------------------------------
static void tf2x32(uint32_t k0, uint32_t k1, uint32_t c0, uint32_t c1,
                   uint32_t* o0, uint32_t* o1)
{
    uint32_t ks[3] = { k0, k1, k0 ^ k1 ^ 0x1BD11BDAu };
    uint32_t x0 = c0 + ks[0];
    uint32_t x1 = c1 + ks[1];
    static const int rot[2][4] = { {13, 15, 26, 6}, {17, 29, 16, 24} };
    for (int i = 0; i < 5; i++) {
        const int* r = rot[i & 1];
        for (int j = 0; j < 4; j++) {
            x0 += x1;
            x1 = (x1 << r[j]) | (x1 >> (32 - r[j]));
            x1 ^= x0;
        }
        x0 += ks[(i + 1) % 3];
        x1 += ks[(i + 2) % 3] + (uint32_t)(i + 1);
    }
    *o0 = x0;
    *o1 = x1;
}

static void compute_start(int* s)
{
    uint32_t K0, K1;
    tf2x32(0u, 0u, 0u, 1u, &K0, &K1);       // fold_in(key(0), 1)
    uint32_t b0, b1;
    tf2x32(K0, K1, 0u, 1u, &b0, &b1);       // partitionable split, lower key
    for (int i = 0; i < BB; i++) {
        uint32_t y0, y1;
        tf2x32(b0, b1, 0u, (uint32_t)i, &y0, &y1);
        s[i] = (int)((y0 ^ y1) & (uint32_t)(NN - 1));   // span = 2^17
    }
}

extern "C" void kernel_launch(void* const* d_in, const int* in_sizes, int n_in,
                              void* d_out, int out_size)
{
    const float* xyz = (const float*)d_in[0];
    float* out = (float*)d_out;

    StartArg st;
    compute_start(st.s);

    cudaFuncSetAttribute(fps_main_kernel,
                         cudaFuncAttributeMaxDynamicSharedMemorySize,
                         (int)SMEM_BYTES);

    fps_clear_kernel<<<1, 256>>>();
    fps_main_kernel<<<GRID, NT, SMEM_BYTES>>>(xyz, out, st);
}

// round 8
// speedup vs baseline: 1.4440x; 1.0024x over previous
#include <cuda_runtime.h>
#include <cstdint>

// FPSampler: farthest point sampling, B=16, N=131072, npoint=1024.
// 128 CTAs, 512 threads, 1 CTA/SM single wave. Each CTA serves TWO batches
// (A = cta>>4, B = A+8), 16 CTAs per batch, 8192 points per chain per CTA.
// The two independent chains are software-pipelined so each chain's cross-CTA
// exchange latency is hidden under the other chain's compute phase.
// Exchange substrate: R7's proven tagged u64 slots + warp-0-uniform poll.

#define BB 16
#define NN 131072
#define NP 1024
#define GG 16                    // CTAs per batch group
#define PTS (NN / GG)            // 8192 points per chain per CTA
#define NT 512                   // threads per CTA
#define NW (NT / 32)             // 16 warps
#define JJ 4                     // float4 chunks per thread (4*4 = 16 points)
#define GRID 128                 // physical CTAs
#define SMEM_BYTES (6 * PTS * sizeof(float))   // 2 chains x 3 planes = 192KB

// Slot: 4 aligned u64 words, EACH self-tagged with seq (=it).
//   w0 = [seq:15 bits 49..63 | val:32 bits 17..48 | idx:17 bits 0..16]
//   wx/wy/wz = (seq << 32) | f32_bits
struct alignas(32) Slot4 {
    unsigned long long w0, wx, wy, wz;
};

__device__ Slot4 g_slot[2][BB][GG];

struct StartArg { int s[BB]; };

__global__ void fps_clear_kernel() {
    unsigned long long* p = (unsigned long long*)g_slot;
    int n = 2 * BB * GG * 4;
    for (int i = threadIdx.x; i < n; i += blockDim.x) p[i] = 0ull;
}

// ---------------- helpers ---------------------------------------------------
__device__ __forceinline__ unsigned redux_max_u32(unsigned v) {
    unsigned r;
    asm("redux.sync.max.u32 %0, %1, 0xffffffff;" : "=r"(r) : "r"(v));
    return r;
}
__device__ __forceinline__ unsigned long long f2add(unsigned long long a,
                                                    unsigned long long b) {
    unsigned long long r;
    asm("add.rn.f32x2 %0, %1, %2;" : "=l"(r) : "l"(a), "l"(b));
    return r;
}
__device__ __forceinline__ unsigned long long f2mul(unsigned long long a,
                                                    unsigned long long b) {
    unsigned long long r;
    asm("mul.rn.f32x2 %0, %1, %2;" : "=l"(r) : "l"(a), "l"(b));
    return r;
}
__device__ __forceinline__ unsigned long long pack2(float a, float b) {
    unsigned long long r;
    asm("mov.b64 %0, {%1, %2};" : "=l"(r) : "f"(a), "f"(b));
    return r;
}
__device__ __forceinline__ void unpack2(unsigned long long v, float& a, float& b) {
    asm("mov.b64 {%0, %1}, %2;" : "=f"(a), "=f"(b) : "l"(v));
}
__device__ __forceinline__ void st_cg_u64(void* p, unsigned long long v) {
    asm volatile("st.global.cg.u64 [%0], %1;" :: "l"(p), "l"(v) : "memory");
}
__device__ __forceinline__ unsigned long long ld_cg_u64(const void* p) {
    unsigned long long v;
    asm volatile("ld.global.cg.u64 %0, [%1];" : "=l"(v) : "l"(p) : "memory");
    return v;
}

// Distance update + warp-level argmax for one chain. Returns (warp max value
// bits, warp max ~idx). Bit-exact reference math: scalar-equivalent rn ops via
// f32x2, (dx*dx + dy*dy) + dz*dz, fminf fold, first-index tie-break.
__device__ __forceinline__ void compute_chain(
    const ulonglong2* __restrict__ xs2, const ulonglong2* __restrict__ ys2,
    const ulonglong2* __restrict__ zs2, float (&dist)[JJ][4],
    float cx, float cy, float cz, int t, int base,
    unsigned& maxb_out, unsigned& maxc_out)
{
    const unsigned long long ncx2 = pack2(-cx, -cx);
    const unsigned long long ncy2 = pack2(-cy, -cy);
    const unsigned long long ncz2 = pack2(-cz, -cz);

    float bv0 = -1.0f, bv1 = -1.0f, bv2 = -1.0f, bv3 = -1.0f;
#pragma unroll
    for (int j = 0; j < JJ; j++) {
        const int c0 = j * NT + t;            // chunk; points 4c0..4c0+3
        ulonglong2 xq = xs2[c0];
        ulonglong2 yq = ys2[c0];
        ulonglong2 zq = zs2[c0];

        unsigned long long dxa = f2add(xq.x, ncx2);
        unsigned long long dxb = f2add(xq.y, ncx2);
        unsigned long long dya = f2add(yq.x, ncy2);
        unsigned long long dyb = f2add(yq.y, ncy2);
        unsigned long long dza = f2add(zq.x, ncz2);
        unsigned long long dzb = f2add(zq.y, ncz2);
        unsigned long long sa =
            f2add(f2add(f2mul(dxa, dxa), f2mul(dya, dya)), f2mul(dza, dza));
        unsigned long long sb =
            f2add(f2add(f2mul(dxb, dxb), f2mul(dyb, dyb)), f2mul(dzb, dzb));

        float d0, d1, d2, d3;
        unpack2(sa, d0, d1);
        unpack2(sb, d2, d3);

        float nd;
        nd = fminf(dist[j][0], d0); dist[j][0] = nd; bv0 = fmaxf(bv0, nd);
        nd = fminf(dist[j][1], d1); dist[j][1] = nd; bv1 = fmaxf(bv1, nd);
        nd = fminf(dist[j][2], d2); dist[j][2] = nd; bv2 = fmaxf(bv2, nd);
        nd = fminf(dist[j][3], d3); dist[j][3] = nd; bv3 = fmaxf(bv3, nd);
    }
    const float bestv = fmaxf(fmaxf(bv0, bv1), fmaxf(bv2, bv3));

    const unsigned mybits = __float_as_uint(bestv);   // d>=0 -> monotone bits
    const unsigned maxb = redux_max_u32(mybits);
    const float maxvf = __uint_as_float(maxb);
    unsigned cand = 0;    // max of ~idx over matches == smallest matching idx
#pragma unroll
    for (int j = 0; j < JJ; j++)
#pragma unroll
        for (int e = 0; e < 4; e++) {
            unsigned ni = 0xFFFFFFFFu - (unsigned)(base + 4 * (j * NT + t) + e);
            if (dist[j][e] == maxvf) cand = (cand > ni) ? cand : ni;
        }
    maxb_out = maxb;
    maxc_out = redux_max_u32(cand);                   // tie -> smallest idx
}

// Warp-0 CTA reduce over wred + publish this CTA's winner (lane 0).
__device__ __forceinline__ void reduce_publish(
    const unsigned long long* wred, int lane, int it, int buf, int batch,
    int rank, int base, const float* xs, const float* ys, const float* zs)
{
    unsigned long long wv = (lane < NW) ? wred[lane] : 0ull;
    unsigned hb = (unsigned)(wv >> 32);
    unsigned maxhb = redux_max_u32(hb);
    unsigned lb = (hb == maxhb) ? (unsigned)(wv & 0xFFFFFFFFull) : 0u;
    unsigned maxlb = redux_max_u32(lb);

    if (lane == 0) {
        unsigned gidx = 0xFFFFFFFFu - maxlb;          // batch-global winner idx
        int lp = (int)gidx - base;                    // CTA-local winner
        const unsigned long long seq32 = ((unsigned long long)it << 32);
        Slot4* sl = &g_slot[buf][batch][rank];
        st_cg_u64(&sl->wx, seq32 | __float_as_uint(xs[lp]));
        st_cg_u64(&sl->wy, seq32 | __float_as_uint(ys[lp]));
        st_cg_u64(&sl->wz, seq32 | __float_as_uint(zs[lp]));
        st_cg_u64(&sl->w0, ((unsigned long long)it << 49) |
                           ((unsigned long long)maxhb << 17) |
                           (unsigned long long)(gidx & 0x1FFFFu));
    }
    __syncwarp();
}

// Warp-0 uniform tagged poll over GG slots; group winner -> (x,y,z,idx).
__device__ __forceinline__ void poll_group(
    int lane, int it, int buf, int batch,
    unsigned& ox, unsigned& oy, unsigned& oz, unsigned& oidx)
{
    const Slot4* sl = &g_slot[buf][batch][lane & (GG - 1)];
    unsigned long long w0 = 0, wx = 0, wy = 0, wz = 0;
    const unsigned u = (unsigned)it;
    bool ok;
    do {
        if (lane < GG) {
            w0 = ld_cg_u64(&sl->w0);
            wx = ld_cg_u64(&sl->wx);
            wy = ld_cg_u64(&sl->wy);
            wz = ld_cg_u64(&sl->wz);
            ok = ((unsigned)(w0 >> 49) == u) &
                 ((unsigned)(wx >> 32) == u) &
                 ((unsigned)(wy >> 32) == u) &
                 ((unsigned)(wz >> 32) == u);
        } else {
            ok = true;
        }
    } while (!__all_sync(0xFFFFFFFFu, ok));

    unsigned val_j = 0u, nidx_j = 0u, xb_j = 0u, yb_j = 0u, zb_j = 0u;
    if (lane < GG) {
        val_j  = (unsigned)((w0 >> 17) & 0xFFFFFFFFull);
        nidx_j = 0xFFFFFFFFu - (unsigned)(w0 & 0x1FFFFull);
        xb_j = (unsigned)wx;
        yb_j = (unsigned)wy;
        zb_j = (unsigned)wz;
    }
    const unsigned maxh = redux_max_u32(val_j);
    const unsigned lj = (val_j == maxh) ? nidx_j : 0u;
    const unsigned maxl = redux_max_u32(lj);          // tie -> smallest idx
    const unsigned m = __ballot_sync(0xFFFFFFFFu,
                        lane < GG && val_j == maxh && nidx_j == maxl);
    const int wl = __ffs((int)m) - 1;
    ox = __shfl_sync(0xFFFFFFFFu, xb_j, wl);
    oy = __shfl_sync(0xFFFFFFFFu, yb_j, wl);
    oz = __shfl_sync(0xFFFFFFFFu, zb_j, wl);
    oidx = 0xFFFFFFFFu - maxl;
}

__global__ void __launch_bounds__(NT, 1)
fps_main_kernel(const float* __restrict__ xyz, float* __restrict__ out, StartArg st)
{
    extern __shared__ float smem[];
    float* xsA = smem;
    float* ysA = smem + PTS;
    float* zsA = smem + 2 * PTS;
    float* xsB = smem + 3 * PTS;
    float* ysB = smem + 4 * PTS;
    float* zsB = smem + 5 * PTS;
    const ulonglong2* xsA2 = (const ulonglong2*)xsA;
    const ulonglong2* ysA2 = (const ulonglong2*)ysA;
    const ulonglong2* zsA2 = (const ulonglong2*)zsA;
    const ulonglong2* xsB2 = (const ulonglong2*)xsB;
    const ulonglong2* ysB2 = (const ulonglong2*)ysB;
    const ulonglong2* zsB2 = (const ulonglong2*)zsB;

    __shared__ unsigned long long wred[NW];
    __shared__ unsigned bcA[4], bcB[4];   // x,y,z,idx

    const int cta  = blockIdx.x;
    const int bA   = cta >> 4;            // batch A: 0..7
    const int bB   = bA + 8;              // batch B: 8..15
    const int rank = cta & (GG - 1);      // rank within group: 0..15
    const int t    = threadIdx.x;
    const int lane = t & 31;
    const int warp = t >> 5;
    const int base = rank * PTS;          // first batch-global point index

    const float* xbA = xyz + (size_t)bA * NN * 3;
    const float* xbB = xyz + (size_t)bB * NN * 3;
    float* out_xyz = out;
    float* out_idx = out + (size_t)BB * NP * 3;

    // One-time load of both slabs into SMEM planes.
    for (int p = t; p < PTS; p += NT) {
        const float* sA = xbA + (size_t)(base + p) * 3;
        xsA[p] = sA[0]; ysA[p] = sA[1]; zsA[p] = sA[2];
        const float* sB = xbB + (size_t)(base + p) * 3;
        xsB[p] = sB[0]; ysB[p] = sB[1]; zsB[p] = sB[2];
    }

    float distA[JJ][4], distB[JJ][4];
#pragma unroll
    for (int j = 0; j < JJ; j++)
#pragma unroll
        for (int e = 0; e < 4; e++) { distA[j][e] = 1e10f; distB[j][e] = 1e10f; }

    // First centroids.
    const int fiA = st.s[bA];
    const int fiB = st.s[bB];
    float cxA = xbA[(size_t)fiA * 3 + 0];
    float cyA = xbA[(size_t)fiA * 3 + 1];
    float czA = xbA[(size_t)fiA * 3 + 2];
    float cxB = xbB[(size_t)fiB * 3 + 0];
    float cyB = xbB[(size_t)fiB * 3 + 1];
    float czB = xbB[(size_t)fiB * 3 + 2];

    if (rank == 0 && t == 0) {
        size_t oA = (size_t)bA * NP * 3;
        out_xyz[oA + 0] = cxA; out_xyz[oA + 1] = cyA; out_xyz[oA + 2] = czA;
        out_idx[(size_t)bA * NP] = (float)fiA;
        size_t oB = (size_t)bB * NP * 3;
        out_xyz[oB + 0] = cxB; out_xyz[oB + 1] = cyB; out_xyz[oB + 2] = czB;
        out_idx[(size_t)bB * NP] = (float)fiB;
    }
    __syncthreads();

    for (int it = 1; it < NP; it++) {
        const int buf  = it & 1;
        const int bufp = (it - 1) & 1;

        // ---- phase 1: compute chain A with centroidA(it-1) ----
        {
            unsigned mb, mc;
            compute_chain(xsA2, ysA2, zsA2, distA, cxA, cyA, czA, t, base, mb, mc);
            if (lane == 0) wred[warp] = ((unsigned long long)mb << 32) | mc;
        }
        __syncthreads();

        // ---- phase 2: warp0 reduce+publish A(it); poll B(it-1) ----
        if (warp == 0) {
            reduce_publish(wred, lane, it, buf, bA, rank, base, xsA, ysA, zsA);
            if (it >= 2) {
                unsigned ox, oy, oz, oidx;
                poll_group(lane, it - 1, bufp, bB, ox, oy, oz, oidx);
                if (lane == 0) {
                    bcB[0] = ox; bcB[1] = oy; bcB[2] = oz; bcB[3] = oidx;
                    if (rank == 0) {
                        size_t o3 = ((size_t)bB * NP + (it - 1)) * 3;
                        out_xyz[o3 + 0] = __uint_as_float(ox);
                        out_xyz[o3 + 1] = __uint_as_float(oy);
                        out_xyz[o3 + 2] = __uint_as_float(oz);
                        out_idx[(size_t)bB * NP + (it - 1)] = (float)oidx;
                    }
                }
            }
        }
        __syncthreads();
        if (it >= 2) {
            cxB = __uint_as_float(bcB[0]);
            cyB = __uint_as_float(bcB[1]);
            czB = __uint_as_float(bcB[2]);
        }

        // ---- phase 3: compute chain B with centroidB(it-1) ----
        {
            unsigned mb, mc;
            compute_chain(xsB2, ysB2, zsB2, distB, cxB, cyB, czB, t, base, mb, mc);
            if (lane == 0) wred[warp] = ((unsigned long long)mb << 32) | mc;
        }
        __syncthreads();

        // ---- phase 4: warp0 reduce+publish B(it); poll A(it) ----
        if (warp == 0) {
            reduce_publish(wred, lane, it, buf, bB, rank, base, xsB, ysB, zsB);
            {
                unsigned ox, oy, oz, oidx;
                poll_group(lane, it, buf, bA, ox, oy, oz, oidx);
                if (lane == 0) {
                    bcA[0] = ox; bcA[1] = oy; bcA[2] = oz; bcA[3] = oidx;
                    if (rank == 0) {
                        size_t o3 = ((size_t)bA * NP + it) * 3;
                        out_xyz[o3 + 0] = __uint_as_float(ox);
                        out_xyz[o3 + 1] = __uint_as_float(oy);
                        out_xyz[o3 + 2] = __uint_as_float(oz);
                        out_idx[(size_t)bA * NP + it] = (float)oidx;
                    }
                }
            }
        }
        __syncthreads();
        cxA = __uint_as_float(bcA[0]);
        cyA = __uint_as_float(bcA[1]);
        czA = __uint_as_float(bcA[2]);
    }

    // ---- epilogue: retrieve and write chain B's final winner B(NP-1) ----
    if (warp == 0) {
        unsigned ox, oy, oz, oidx;
        poll_group(lane, NP - 1, (NP - 1) & 1, bB, ox, oy, oz, oidx);
        if (lane == 0 && rank == 0) {
            size_t o3 = ((size_t)bB * NP + (NP - 1)) * 3;
            out_xyz[o3 + 0] = __uint_as_float(ox);
            out_xyz[o3 + 1] = __uint_as_float(oy);
            out_xyz[o3 + 2] = __uint_as_float(oz);
            out_idx[(size_t)bB * NP + (NP - 1)] = (float)oidx;
        }
    }
}

// ---------------------------------------------------------------------------
// Host-side reproduction of JAX Threefry RNG for `start` (verified exact R1):
//   start = randint(fold_in(key(0), 1), (16,), 0, 131072), partitionable mode.
// ---------------------------------------------------------------------------
static void tf2x32(uint32_t k0, uint32_t k1, uint32_t c0, uint32_t c1,
                   uint32_t* o0, uint32_t* o1)
{
    uint32_t ks[3] = { k0, k1, k0 ^ k1 ^ 0x1BD11BDAu };
    uint32_t x0 = c0 + ks[0];
    uint32_t x1 = c1 + ks[1];
    static const int rot[2][4] = { {13, 15, 26, 6}, {17, 29, 16, 24} };
    for (int i = 0; i < 5; i++) {
        const int* r = rot[i & 1];
        for (int j = 0; j < 4; j++) {
            x0 += x1;
            x1 = (x1 << r[j]) | (x1 >> (32 - r[j]));
            x1 ^= x0;
        }
        x0 += ks[(i + 1) % 3];
        x1 += ks[(i + 2) % 3] + (uint32_t)(i + 1);
    }
    *o0 = x0;
    *o1 = x1;
}

static void compute_start(int* s)
{
    uint32_t K0, K1;
    tf2x32(0u, 0u, 0u, 1u, &K0, &K1);       // fold_in(key(0), 1)
    uint32_t b0, b1;
    tf2x32(K0, K1, 0u, 1u, &b0, &b1);       // partitionable split, lower key
    for (int i = 0; i < BB; i++) {
        uint32_t y0, y1;
        tf2x32(b0, b1, 0u, (uint32_t)i, &y0, &y1);
        s[i] = (int)((y0 ^ y1) & (uint32_t)(NN - 1));   // span = 2^17
    }
}

extern "C" void kernel_launch(void* const* d_in, const int* in_sizes, int n_in,
                              void* d_out, int out_size)
{
    const float* xyz = (const float*)d_in[0];
    float* out = (float*)d_out;

    StartArg st;
    compute_start(st.s);

    cudaFuncSetAttribute(fps_main_kernel,
                         cudaFuncAttributeMaxDynamicSharedMemorySize,
                         (int)SMEM_BYTES);

    fps_clear_kernel<<<1, 256>>>();
    fps_main_kernel<<<GRID, NT, SMEM_BYTES>>>(xyz, out, st);
}